// round 7
// baseline (speedup 1.0000x reference)
#include <cuda_runtime.h>
#include <cuda_fp16.h>
#include <cstdint>

// Shapes (fixed by the problem)
#define B_ 64
#define S_ 197
#define D_ 768
#define P_ 196
#define M_ (B_ * S_)   // 12608 = 64 * 197

// Device scratch (no cudaMalloc allowed)
__device__ __half g_xs[(size_t)M_ * D_];    // weighted-gathered x, fp16
__device__ __half g_wt[(size_t)D_ * D_];    // Wv^T in fp16: g_wt[n][k]
__device__ float  g_ws[M_];                 // per-row weight sum

__device__ __forceinline__ uint32_t smem_u32(const void* p) {
    uint32_t a;
    asm("{ .reg .u64 t; cvta.to.shared.u64 t, %1; cvt.u32.u64 %0, t; }"
        : "=r"(a) : "l"(p));
    return a;
}
__device__ __forceinline__ void cp_async16(uint32_t dst, const void* src) {
    asm volatile("cp.async.cg.shared.global [%0], [%1], 16;"
                 :: "r"(dst), "l"(src));
}
#define CP_COMMIT() asm volatile("cp.async.commit_group;" ::: "memory")
#define CP_WAIT(n)  asm volatile("cp.async.wait_group %0;" :: "n"(n) : "memory")

__device__ __forceinline__ void mma_f16(float* d, const uint32_t* a, const uint32_t* b)
{
    asm volatile(
        "mma.sync.aligned.m16n8k16.row.col.f32.f16.f16.f32 "
        "{%0,%1,%2,%3}, {%4,%5,%6,%7}, {%8,%9}, {%0,%1,%2,%3};"
        : "+f"(d[0]), "+f"(d[1]), "+f"(d[2]), "+f"(d[3])
        : "r"(a[0]), "r"(a[1]), "r"(a[2]), "r"(a[3]), "r"(b[0]), "r"(b[1]));
}

// ---------------------------------------------------------------------------
// Fused prep: blocks [0, M_) do the weighted gather of x -> xs (fp16) + wsum;
// blocks [M_, M_+576) transpose+convert Wv -> Wt[n][k] fp16.
// ---------------------------------------------------------------------------
__device__ __forceinline__ int wrap197(int i)
{
    int r = i % S_;
    return (r < 0) ? r + S_ : r;
}

__global__ __launch_bounds__(192) void prep_kernel(
    const float* __restrict__ x, const int* __restrict__ img_ids,
    const float* __restrict__ avgs, const float* __restrict__ stds,
    const float* __restrict__ noise, const float* __restrict__ W,
    __half* __restrict__ xs, __half* __restrict__ wt, float* __restrict__ wsum)
{
    __shared__ float tile[32][33];
    const int bid = blockIdx.x;
    const int tid = threadIdx.x;

    if (bid >= M_) {
        // ---- transpose tile of W ----
        const int t  = bid - M_;        // 0..575
        const int tx = t % 24;
        const int ty = t / 24;
        const int lx = tid & 31;
        const int ly = tid >> 5;        // 0..5
#pragma unroll
        for (int i = 0; i < 36; i += 6) {
            const int r = ly + i;
            if (r < 32)
                tile[r][lx] = W[(size_t)(ty * 32 + r) * D_ + tx * 32 + lx];
        }
        __syncthreads();
#pragma unroll
        for (int i = 0; i < 36; i += 6) {
            const int r = ly + i;
            if (r < 32)
                wt[(size_t)(tx * 32 + r) * D_ + ty * 32 + lx] =
                    __float2half_rn(tile[lx][r]);
        }
        return;
    }

    // ---- gather row ----
    const int row = bid;
    const int b = row / S_;
    const int s = row - b * S_;
    const int t = tid;                  // 0..191, 4 elements each

    uint2* orow = (uint2*)(xs + (size_t)row * D_) + t;
    if (s == 0) {
        *orow = make_uint2(0u, 0u);
        if (t == 0) wsum[row] = 0.0f;
        return;
    }
    const int p = s - 1;
    const int id = img_ids[b];
    const float nx = noise[(size_t)(b * 2 + 0) * P_ + p];
    const float ny = noise[(size_t)(b * 2 + 1) * P_ + p];
    const size_t gb = (size_t)id * 2 * P_;
    const float ax = avgs[gb + p],  ay = avgs[gb + P_ + p];
    const float sx = stds[gb + p],  sy = stds[gb + P_ + p];

    const float kx = (nx - ax) / sx;
    const float ky = (ny - ay) / sy;
    const float x1 = ceilf(kx),  x2 = floorf(kx);
    const float y1 = ceilf(ky),  y2 = floorf(ky);
    const float wx1 = 1.0f - fabsf(x1 - kx);
    const float wx2 = 1.0f - fabsf(x2 - kx);
    const float wy1 = 1.0f - fabsf(y1 - ky);
    const float wy2 = 1.0f - fabsf(y2 - ky);
    const float w11 = wx1 * wy1, w21 = wx2 * wy1;
    const float w12 = wx1 * wy2, w22 = wx2 * wy2;

    const int i11 = wrap197((int)(14.0f * y1 + x1));
    const int i21 = wrap197((int)(14.0f * y1 + x2));
    const int i12 = wrap197((int)(14.0f * y2 + x1));
    const int i22 = wrap197((int)(14.0f * y2 + x2));

    const float4* xb = (const float4*)x + (size_t)b * S_ * (D_ / 4);
    const float4 a = xb[(size_t)i11 * (D_ / 4) + t];
    const float4 c = xb[(size_t)i21 * (D_ / 4) + t];
    const float4 d = xb[(size_t)i12 * (D_ / 4) + t];
    const float4 e = xb[(size_t)i22 * (D_ / 4) + t];

    float4 r;
    r.x = w11 * a.x + w21 * c.x + w12 * d.x + w22 * e.x;
    r.y = w11 * a.y + w21 * c.y + w12 * d.y + w22 * e.y;
    r.z = w11 * a.z + w21 * c.z + w12 * d.z + w22 * e.z;
    r.w = w11 * a.w + w21 * c.w + w12 * d.w + w22 * e.w;

    __half2 h0 = __floats2half2_rn(r.x, r.y);
    __half2 h1 = __floats2half2_rn(r.z, r.w);
    uint2 o;
    o.x = *(uint32_t*)&h0;
    o.y = *(uint32_t*)&h1;
    *orow = o;

    if (t == 0) wsum[row] = w11 + w21 + w12 + w22;
}

// ---------------------------------------------------------------------------
// FP16 tensor GEMM: out[M_,768] = xs @ Wt^T + wsum*bias (cls rows = 1.0)
// CTA 128x128, BK=32, 4-stage cp.async, single barrier per stage,
// 8 warps (2m x 4n), 64x32 warp tiles. XOR-swizzled 64B smem rows ->
// conflict-free (sel = g>>1 for all fragments). 64KB smem -> 3 CTAs/SM.
// ---------------------------------------------------------------------------
#define BK     32
#define NSTG   24          // 768/32
#define STAGES 4
#define TILE_BYTES (128 * 64)              // 8192 per operand per stage
#define STAGE_B (2 * TILE_BYTES)           // 16384
#define SMEM_TOTAL (STAGES * STAGE_B)      // 65536

__global__ __launch_bounds__(256, 3) void gemm_f16(
    const __half* __restrict__ A, const __half* __restrict__ Bt,
    const float* __restrict__ bias, const float* __restrict__ wsum,
    float* __restrict__ C)
{
    extern __shared__ char smem[];
    const uint32_t sb = smem_u32(smem);

    const int tid  = threadIdx.x;
    const int wid  = tid >> 5;
    const int lane = tid & 31;
    const int g    = lane >> 2;       // 0..7
    const int t4   = lane & 3;        // 0..3
    const int sel  = g >> 1;          // swizzle selector (0..3)
    const int wm   = wid & 1;         // 2 warp rows -> 64 m each
    const int wn   = wid >> 1;        // 4 warp cols -> 32 n each
    const int m0 = blockIdx.y * 128;
    const int n0 = blockIdx.x * 128;

    // cp.async maps: 512 16B chunks per operand tile, 2 per thread each
    const int r0 = tid >> 2,         c0 = tid & 3;
    const int r1 = (tid + 256) >> 2, c1 = (tid + 256) & 3;

    int ga0 = m0 + r0; if (ga0 >= M_) ga0 = M_ - 1;
    int ga1 = m0 + r1; if (ga1 >= M_) ga1 = M_ - 1;
    const __half* Ap0 = A + (size_t)ga0 * D_ + c0 * 8;
    const __half* Ap1 = A + (size_t)ga1 * D_ + c1 * 8;
    const __half* Bp0 = Bt + (size_t)(n0 + r0) * D_ + c0 * 8;
    const __half* Bp1 = Bt + (size_t)(n0 + r1) * D_ + c1 * 8;

    const uint32_t aDst0 = sb + (uint32_t)(r0 * 64 + ((c0 ^ ((r0 >> 1) & 3)) << 4));
    const uint32_t aDst1 = sb + (uint32_t)(r1 * 64 + ((c1 ^ ((r1 >> 1) & 3)) << 4));
    const uint32_t bDst0 = aDst0 + TILE_BYTES;
    const uint32_t bDst1 = aDst1 + TILE_BYTES;

    float acc[4][4][4];
#pragma unroll
    for (int i = 0; i < 4; i++)
#pragma unroll
        for (int j = 0; j < 4; j++)
#pragma unroll
            for (int r = 0; r < 4; r++) acc[i][j][r] = 0.0f;

    // prologue: stages 0..STAGES-2
#pragma unroll
    for (int s = 0; s < STAGES - 1; s++) {
        const int k0 = s * BK;
        const uint32_t so = (uint32_t)(s * STAGE_B);
        cp_async16(aDst0 + so, Ap0 + k0);
        cp_async16(aDst1 + so, Ap1 + k0);
        cp_async16(bDst0 + so, Bp0 + k0);
        cp_async16(bDst1 + so, Bp1 + k0);
        CP_COMMIT();
    }

    for (int s = 0; s < NSTG; s++) {
        CP_WAIT(STAGES - 2);          // stage-s tile landed
        __syncthreads();              // all warps done reading slot (s-1)%4

        const int sl = s + STAGES - 1;
        if (sl < NSTG) {
            const int k0 = sl * BK;
            const uint32_t so = (uint32_t)((sl & (STAGES - 1)) * STAGE_B);
            cp_async16(aDst0 + so, Ap0 + k0);
            cp_async16(aDst1 + so, Ap1 + k0);
            cp_async16(bDst0 + so, Bp0 + k0);
            cp_async16(bDst1 + so, Bp1 + k0);
        }
        CP_COMMIT();                  // empty group in tail keeps count right

        const char* Ab = smem + (s & (STAGES - 1)) * STAGE_B;
        const char* Bb = Ab + TILE_BYTES;
#pragma unroll
        for (int kk = 0; kk < 2; kk++) {            // two k16 steps in BK=32
            const uint32_t o0 = (uint32_t)((((2 * kk)     ^ sel) << 4) + t4 * 4);
            const uint32_t o1 = (uint32_t)((((2 * kk + 1) ^ sel) << 4) + t4 * 4);
            uint32_t a[4][4], b[4][2];
#pragma unroll
            for (int fm = 0; fm < 4; fm++) {
                const char* p0 = Ab + (wm * 64 + fm * 16 + g) * 64;
                const char* p1 = p0 + 8 * 64;       // row+8: same sel
                a[fm][0] = *(const uint32_t*)(p0 + o0);
                a[fm][1] = *(const uint32_t*)(p1 + o0);
                a[fm][2] = *(const uint32_t*)(p0 + o1);
                a[fm][3] = *(const uint32_t*)(p1 + o1);
            }
#pragma unroll
            for (int fn = 0; fn < 4; fn++) {
                const char* p = Bb + (wn * 32 + fn * 8 + g) * 64;
                b[fn][0] = *(const uint32_t*)(p + o0);
                b[fn][1] = *(const uint32_t*)(p + o1);
            }
#pragma unroll
            for (int fm = 0; fm < 4; fm++)
#pragma unroll
                for (int fn = 0; fn < 4; fn++)
                    mma_f16(acc[fm][fn], a[fm], b[fn]);
        }
    }

    // epilogue: out = acc + wsum[row]*bias[col]; class-token rows = 1.0
#pragma unroll
    for (int fm = 0; fm < 4; fm++) {
        const int row0 = m0 + wm * 64 + fm * 16 + g;
        const int row1 = row0 + 8;
        const bool ok0 = row0 < M_;
        const bool ok1 = row1 < M_;
        const bool cls0 = (row0 % S_) == 0;
        const bool cls1 = (row1 % S_) == 0;
        const float ws0 = ok0 ? wsum[row0] : 0.0f;
        const float ws1 = ok1 ? wsum[row1] : 0.0f;
#pragma unroll
        for (int fn = 0; fn < 4; fn++) {
            const int col = n0 + wn * 32 + fn * 8 + t4 * 2;
            const float b0 = bias[col];
            const float b1 = bias[col + 1];
            if (ok0) {
                float2 o;
                o.x = cls0 ? 1.0f : acc[fm][fn][0] + ws0 * b0;
                o.y = cls0 ? 1.0f : acc[fm][fn][1] + ws0 * b1;
                *(float2*)(C + (size_t)row0 * D_ + col) = o;
            }
            if (ok1) {
                float2 o;
                o.x = cls1 ? 1.0f : acc[fm][fn][2] + ws1 * b0;
                o.y = cls1 ? 1.0f : acc[fm][fn][3] + ws1 * b1;
                *(float2*)(C + (size_t)row1 * D_ + col) = o;
            }
        }
    }
}

// ---------------------------------------------------------------------------
// Inputs (metadata order): 0:x 1:img_ids 2:mask 3:Wq 4:bq 5:Wk 6:bk
//                          7:Wv 8:bv 9:avgs 10:std_devs 11:noise
// q/k/softmax are dead (softmax over singleton axis == 1): out = sampled v,
// and sampling commutes with the linear map -> gather x first, then one GEMM.
// ---------------------------------------------------------------------------
extern "C" void kernel_launch(void* const* d_in, const int* in_sizes, int n_in,
                              void* d_out, int out_size)
{
    const float* x       = (const float*)d_in[0];
    const int*   img_ids = (const int*)d_in[1];
    const float* Wv      = (const float*)d_in[7];
    const float* bv      = (const float*)d_in[8];
    const float* avgs    = (const float*)d_in[9];
    const float* stds    = (const float*)d_in[10];
    const float* noise   = (const float*)d_in[11];
    float* out = (float*)d_out;

    __half* xs = nullptr;
    __half* wt = nullptr;
    float*  ws = nullptr;
    cudaGetSymbolAddress((void**)&xs, g_xs);
    cudaGetSymbolAddress((void**)&wt, g_wt);
    cudaGetSymbolAddress((void**)&ws, g_ws);

    cudaFuncSetAttribute(gemm_f16, cudaFuncAttributeMaxDynamicSharedMemorySize,
                         SMEM_TOTAL);

    prep_kernel<<<M_ + 576, 192>>>(x, img_ids, avgs, stds, noise, Wv, xs, wt, ws);
    gemm_f16<<<dim3(6, 99), 256, SMEM_TOTAL>>>(xs, wt, bv, ws, out);
}

// round 8
// speedup vs baseline: 1.4477x; 1.4477x over previous
#include <cuda_runtime.h>
#include <cuda_fp16.h>
#include <cstdint>

// Shapes (fixed by the problem)
#define B_ 64
#define S_ 197
#define D_ 768
#define P_ 196
#define M_ (B_ * S_)   // 12608 = 64 * 197

// Device scratch (no cudaMalloc allowed)
__device__ __half g_xs[(size_t)M_ * D_];    // weighted-gathered x, fp16
__device__ __half g_wt[(size_t)D_ * D_];    // Wv^T in fp16: g_wt[n][k]
__device__ float  g_ws[M_];                 // per-row weight sum

__device__ __forceinline__ uint32_t smem_u32(const void* p) {
    uint32_t a;
    asm("{ .reg .u64 t; cvta.to.shared.u64 t, %1; cvt.u32.u64 %0, t; }"
        : "=r"(a) : "l"(p));
    return a;
}
__device__ __forceinline__ void cp_async16(uint32_t dst, const void* src) {
    asm volatile("cp.async.cg.shared.global [%0], [%1], 16;"
                 :: "r"(dst), "l"(src));
}
#define CP_COMMIT() asm volatile("cp.async.commit_group;" ::: "memory")
#define CP_WAIT(n)  asm volatile("cp.async.wait_group %0;" :: "n"(n) : "memory")

__device__ __forceinline__ void mma_f16(float* d, const uint32_t* a, const uint32_t* b)
{
    asm volatile(
        "mma.sync.aligned.m16n8k16.row.col.f32.f16.f16.f32 "
        "{%0,%1,%2,%3}, {%4,%5,%6,%7}, {%8,%9}, {%0,%1,%2,%3};"
        : "+f"(d[0]), "+f"(d[1]), "+f"(d[2]), "+f"(d[3])
        : "r"(a[0]), "r"(a[1]), "r"(a[2]), "r"(a[3]), "r"(b[0]), "r"(b[1]));
}

// ---------------------------------------------------------------------------
// Fused prep: blocks [0, M_) do the weighted gather of x -> xs (fp16) + wsum;
// blocks [M_, M_+576) transpose+convert Wv -> Wt[n][k] fp16.
// ---------------------------------------------------------------------------
__device__ __forceinline__ int wrap197(int i)
{
    int r = i % S_;
    return (r < 0) ? r + S_ : r;
}

__global__ __launch_bounds__(192) void prep_kernel(
    const float* __restrict__ x, const int* __restrict__ img_ids,
    const float* __restrict__ avgs, const float* __restrict__ stds,
    const float* __restrict__ noise, const float* __restrict__ W,
    __half* __restrict__ xs, __half* __restrict__ wt, float* __restrict__ wsum)
{
    __shared__ float tile[32][33];
    const int bid = blockIdx.x;
    const int tid = threadIdx.x;

    if (bid >= M_) {
        // ---- transpose tile of W ----
        const int t  = bid - M_;        // 0..575
        const int tx = t % 24;
        const int ty = t / 24;
        const int lx = tid & 31;
        const int ly = tid >> 5;        // 0..5
#pragma unroll
        for (int i = 0; i < 36; i += 6) {
            const int r = ly + i;
            if (r < 32)
                tile[r][lx] = W[(size_t)(ty * 32 + r) * D_ + tx * 32 + lx];
        }
        __syncthreads();
#pragma unroll
        for (int i = 0; i < 36; i += 6) {
            const int r = ly + i;
            if (r < 32)
                wt[(size_t)(tx * 32 + r) * D_ + ty * 32 + lx] =
                    __float2half_rn(tile[lx][r]);
        }
        return;
    }

    // ---- gather row ----
    const int row = bid;
    const int b = row / S_;
    const int s = row - b * S_;
    const int t = tid;                  // 0..191, 4 elements each

    uint2* orow = (uint2*)(xs + (size_t)row * D_) + t;
    if (s == 0) {
        *orow = make_uint2(0u, 0u);
        if (t == 0) wsum[row] = 0.0f;
        return;
    }
    const int p = s - 1;
    const int id = img_ids[b];
    const float nx = noise[(size_t)(b * 2 + 0) * P_ + p];
    const float ny = noise[(size_t)(b * 2 + 1) * P_ + p];
    const size_t gb = (size_t)id * 2 * P_;
    const float ax = avgs[gb + p],  ay = avgs[gb + P_ + p];
    const float sx = stds[gb + p],  sy = stds[gb + P_ + p];

    const float kx = (nx - ax) / sx;
    const float ky = (ny - ay) / sy;
    const float x1 = ceilf(kx),  x2 = floorf(kx);
    const float y1 = ceilf(ky),  y2 = floorf(ky);
    const float wx1 = 1.0f - fabsf(x1 - kx);
    const float wx2 = 1.0f - fabsf(x2 - kx);
    const float wy1 = 1.0f - fabsf(y1 - ky);
    const float wy2 = 1.0f - fabsf(y2 - ky);
    const float w11 = wx1 * wy1, w21 = wx2 * wy1;
    const float w12 = wx1 * wy2, w22 = wx2 * wy2;

    const int i11 = wrap197((int)(14.0f * y1 + x1));
    const int i21 = wrap197((int)(14.0f * y1 + x2));
    const int i12 = wrap197((int)(14.0f * y2 + x1));
    const int i22 = wrap197((int)(14.0f * y2 + x2));

    const float4* xb = (const float4*)x + (size_t)b * S_ * (D_ / 4);
    const float4 a = xb[(size_t)i11 * (D_ / 4) + t];
    const float4 c = xb[(size_t)i21 * (D_ / 4) + t];
    const float4 d = xb[(size_t)i12 * (D_ / 4) + t];
    const float4 e = xb[(size_t)i22 * (D_ / 4) + t];

    float4 r;
    r.x = w11 * a.x + w21 * c.x + w12 * d.x + w22 * e.x;
    r.y = w11 * a.y + w21 * c.y + w12 * d.y + w22 * e.y;
    r.z = w11 * a.z + w21 * c.z + w12 * d.z + w22 * e.z;
    r.w = w11 * a.w + w21 * c.w + w12 * d.w + w22 * e.w;

    __half2 h0 = __floats2half2_rn(r.x, r.y);
    __half2 h1 = __floats2half2_rn(r.z, r.w);
    uint2 o;
    o.x = *(uint32_t*)&h0;
    o.y = *(uint32_t*)&h1;
    *orow = o;

    if (t == 0) wsum[row] = w11 + w21 + w12 + w22;
}

// ---------------------------------------------------------------------------
// FP16 tensor GEMM: out[M_,768] = xs @ Wt^T + wsum*bias (cls rows = 1.0)
// R5 configuration (proven fastest): CTA 128x128, BK=32, 4-stage cp.async,
// 8 warps (2m x 4n), 64x32 warp tiles, 80B-pitch smem, occ 2.
// Persistent over 594 tiles with 592 CTAs: kills the 2-CTA third wave.
// ---------------------------------------------------------------------------
#define BK     32
#define NSTG   24          // 768/32
#define STAGES 4
#define ROWB   80          // bytes per smem row (64 data + 16 pad)
#define TILE_B (128 * ROWB)            // 10240
#define STAGE_B (2 * TILE_B)           // 20480 (A then B)
#define SMEM_TOTAL (STAGES * STAGE_B)  // 81920
#define NTILES 594                      // 99 m-tiles * 6 n-tiles
#define GRID   592                      // 2 * 296 slots (148 SM * occ 2)

__global__ __launch_bounds__(256, 2) void gemm_f16(
    const __half* __restrict__ A, const __half* __restrict__ Bt,
    const float* __restrict__ bias, const float* __restrict__ wsum,
    float* __restrict__ C)
{
    extern __shared__ char smem[];
    const uint32_t sb = smem_u32(smem);

    const int tid  = threadIdx.x;
    const int wid  = tid >> 5;
    const int lane = tid & 31;
    const int g    = lane >> 2;       // 0..7
    const int t4   = lane & 3;        // 0..3
    const int wm   = wid & 1;         // 2 warp rows -> 64 m each
    const int wn   = wid >> 1;        // 4 warp cols -> 32 n each

    // cp.async maps: 512 16B chunks per operand tile, 2 per thread each
    const int r0 = tid >> 2,         c0 = tid & 3;
    const int r1 = (tid + 256) >> 2, c1 = (tid + 256) & 3;

    const uint32_t aDst0 = sb + (uint32_t)(r0 * ROWB + c0 * 16);
    const uint32_t aDst1 = sb + (uint32_t)(r1 * ROWB + c1 * 16);
    const uint32_t bDst0 = aDst0 + TILE_B;
    const uint32_t bDst1 = aDst1 + TILE_B;

    for (int tile = blockIdx.x; tile < NTILES; tile += GRID) {
        const int m0 = (tile / 6) * 128;
        const int n0 = (tile % 6) * 128;

        int ga0 = m0 + r0; if (ga0 >= M_) ga0 = M_ - 1;
        int ga1 = m0 + r1; if (ga1 >= M_) ga1 = M_ - 1;
        const __half* Ap0 = A + (size_t)ga0 * D_ + c0 * 8;
        const __half* Ap1 = A + (size_t)ga1 * D_ + c1 * 8;
        const __half* Bp0 = Bt + (size_t)(n0 + r0) * D_ + c0 * 8;
        const __half* Bp1 = Bt + (size_t)(n0 + r1) * D_ + c1 * 8;

        float acc[4][4][4];
#pragma unroll
        for (int i = 0; i < 4; i++)
#pragma unroll
            for (int j = 0; j < 4; j++)
#pragma unroll
                for (int r = 0; r < 4; r++) acc[i][j][r] = 0.0f;

        // prologue
#pragma unroll
        for (int s = 0; s < STAGES - 1; s++) {
            const int k0 = s * BK;
            const uint32_t so = (uint32_t)(s * STAGE_B);
            cp_async16(aDst0 + so, Ap0 + k0);
            cp_async16(aDst1 + so, Ap1 + k0);
            cp_async16(bDst0 + so, Bp0 + k0);
            cp_async16(bDst1 + so, Bp1 + k0);
            CP_COMMIT();
        }

        for (int s = 0; s < NSTG; s++) {
            const int sl = s + STAGES - 1;
            if (sl < NSTG) {
                const int k0 = sl * BK;
                const uint32_t so = (uint32_t)((sl & (STAGES - 1)) * STAGE_B);
                cp_async16(aDst0 + so, Ap0 + k0);
                cp_async16(aDst1 + so, Ap1 + k0);
                cp_async16(bDst0 + so, Bp0 + k0);
                cp_async16(bDst1 + so, Bp1 + k0);
            }
            CP_COMMIT();
            CP_WAIT(STAGES - 1);
            __syncthreads();

            const char* Ab = smem + (s & (STAGES - 1)) * STAGE_B;
            const char* Bb = Ab + TILE_B;
#pragma unroll
            for (int kk = 0; kk < 2; kk++) {        // two k16 steps in BK=32
                const int kb = kk * 32 + t4 * 4;
                uint32_t a[4][4], b[4][2];
#pragma unroll
                for (int fm = 0; fm < 4; fm++) {
                    const char* p0 = Ab + (wm * 64 + fm * 16 + g) * ROWB + kb;
                    const char* p1 = p0 + 8 * ROWB;
                    a[fm][0] = *(const uint32_t*)(p0);
                    a[fm][1] = *(const uint32_t*)(p1);
                    a[fm][2] = *(const uint32_t*)(p0 + 16);
                    a[fm][3] = *(const uint32_t*)(p1 + 16);
                }
#pragma unroll
                for (int fn = 0; fn < 4; fn++) {
                    const char* p = Bb + (wn * 32 + fn * 8 + g) * ROWB + kb;
                    b[fn][0] = *(const uint32_t*)(p);
                    b[fn][1] = *(const uint32_t*)(p + 16);
                }
#pragma unroll
                for (int fm = 0; fm < 4; fm++)
#pragma unroll
                    for (int fn = 0; fn < 4; fn++)
                        mma_f16(acc[fm][fn], a[fm], b[fn]);
            }
            __syncthreads();
        }

        // epilogue: out = acc + wsum[row]*bias[col]; class-token rows = 1.0
#pragma unroll
        for (int fm = 0; fm < 4; fm++) {
            const int row0 = m0 + wm * 64 + fm * 16 + g;
            const int row1 = row0 + 8;
            const bool ok0 = row0 < M_;
            const bool ok1 = row1 < M_;
            const bool cls0 = (row0 % S_) == 0;
            const bool cls1 = (row1 % S_) == 0;
            const float ws0 = ok0 ? wsum[row0] : 0.0f;
            const float ws1 = ok1 ? wsum[row1] : 0.0f;
#pragma unroll
            for (int fn = 0; fn < 4; fn++) {
                const int col = n0 + wn * 32 + fn * 8 + t4 * 2;
                const float b0 = bias[col];
                const float b1 = bias[col + 1];
                if (ok0) {
                    float2 o;
                    o.x = cls0 ? 1.0f : acc[fm][fn][0] + ws0 * b0;
                    o.y = cls0 ? 1.0f : acc[fm][fn][1] + ws0 * b1;
                    *(float2*)(C + (size_t)row0 * D_ + col) = o;
                }
                if (ok1) {
                    float2 o;
                    o.x = cls1 ? 1.0f : acc[fm][fn][2] + ws1 * b0;
                    o.y = cls1 ? 1.0f : acc[fm][fn][3] + ws1 * b1;
                    *(float2*)(C + (size_t)row1 * D_ + col) = o;
                }
            }
        }
        __syncthreads();   // smem reuse guard before next persistent tile
    }
}

// ---------------------------------------------------------------------------
// Inputs (metadata order): 0:x 1:img_ids 2:mask 3:Wq 4:bq 5:Wk 6:bk
//                          7:Wv 8:bv 9:avgs 10:std_devs 11:noise
// q/k/softmax are dead (softmax over singleton axis == 1): out = sampled v,
// and sampling commutes with the linear map -> gather x first, then one GEMM.
// ---------------------------------------------------------------------------
extern "C" void kernel_launch(void* const* d_in, const int* in_sizes, int n_in,
                              void* d_out, int out_size)
{
    const float* x       = (const float*)d_in[0];
    const int*   img_ids = (const int*)d_in[1];
    const float* Wv      = (const float*)d_in[7];
    const float* bv      = (const float*)d_in[8];
    const float* avgs    = (const float*)d_in[9];
    const float* stds    = (const float*)d_in[10];
    const float* noise   = (const float*)d_in[11];
    float* out = (float*)d_out;

    __half* xs = nullptr;
    __half* wt = nullptr;
    float*  ws = nullptr;
    cudaGetSymbolAddress((void**)&xs, g_xs);
    cudaGetSymbolAddress((void**)&wt, g_wt);
    cudaGetSymbolAddress((void**)&ws, g_ws);

    cudaFuncSetAttribute(gemm_f16, cudaFuncAttributeMaxDynamicSharedMemorySize,
                         SMEM_TOTAL);

    prep_kernel<<<M_ + 576, 192>>>(x, img_ids, avgs, stds, noise, Wv, xs, wt, ws);
    gemm_f16<<<GRID, 256, SMEM_TOTAL>>>(xs, wt, bv, ws, out);
}

// round 9
// speedup vs baseline: 1.8942x; 1.3084x over previous
#include <cuda_runtime.h>
#include <cuda_fp16.h>
#include <cstdint>

// Shapes (fixed by the problem)
#define B_ 64
#define S_ 197
#define D_ 768
#define P_ 196
#define M_ (B_ * S_)   // 12608 = 64 * 197

// Device scratch (no cudaMalloc allowed)
__device__ __half g_xs[(size_t)M_ * D_];    // weighted-gathered x, fp16
__device__ __half g_wt[(size_t)D_ * D_];    // Wv^T in fp16: g_wt[n][k]
__device__ float  g_ws[M_];                 // per-row weight sum

__device__ __forceinline__ uint32_t smem_u32(const void* p) {
    uint32_t a;
    asm("{ .reg .u64 t; cvta.to.shared.u64 t, %1; cvt.u32.u64 %0, t; }"
        : "=r"(a) : "l"(p));
    return a;
}
__device__ __forceinline__ void cp_async16(uint32_t dst, const void* src) {
    asm volatile("cp.async.cg.shared.global [%0], [%1], 16;"
                 :: "r"(dst), "l"(src));
}
#define CP_COMMIT() asm volatile("cp.async.commit_group;" ::: "memory")
#define CP_WAIT(n)  asm volatile("cp.async.wait_group %0;" :: "n"(n) : "memory")

__device__ __forceinline__ void ldsm_x4(uint32_t* r, uint32_t addr) {
    asm volatile("ldmatrix.sync.aligned.m8n8.x4.shared.b16 {%0,%1,%2,%3}, [%4];"
                 : "=r"(r[0]), "=r"(r[1]), "=r"(r[2]), "=r"(r[3]) : "r"(addr));
}
__device__ __forceinline__ void mma_f16(float* d, const uint32_t* a, const uint32_t* b)
{
    asm volatile(
        "mma.sync.aligned.m16n8k16.row.col.f32.f16.f16.f32 "
        "{%0,%1,%2,%3}, {%4,%5,%6,%7}, {%8,%9}, {%0,%1,%2,%3};"
        : "+f"(d[0]), "+f"(d[1]), "+f"(d[2]), "+f"(d[3])
        : "r"(a[0]), "r"(a[1]), "r"(a[2]), "r"(a[3]), "r"(b[0]), "r"(b[1]));
}

// ---------------------------------------------------------------------------
// Fused prep: blocks [0, M_) do the weighted gather of x -> xs (fp16) + wsum;
// blocks [M_, M_+576) transpose+convert Wv -> Wt[n][k] fp16.
// ---------------------------------------------------------------------------
__device__ __forceinline__ int wrap197(int i)
{
    int r = i % S_;
    return (r < 0) ? r + S_ : r;
}

__global__ __launch_bounds__(192) void prep_kernel(
    const float* __restrict__ x, const int* __restrict__ img_ids,
    const float* __restrict__ avgs, const float* __restrict__ stds,
    const float* __restrict__ noise, const float* __restrict__ W,
    __half* __restrict__ xs, __half* __restrict__ wt, float* __restrict__ wsum)
{
    __shared__ float tile[32][33];
    const int bid = blockIdx.x;
    const int tid = threadIdx.x;

    if (bid >= M_) {
        // ---- transpose tile of W ----
        const int t  = bid - M_;        // 0..575
        const int tx = t % 24;
        const int ty = t / 24;
        const int lx = tid & 31;
        const int ly = tid >> 5;        // 0..5
#pragma unroll
        for (int i = 0; i < 36; i += 6) {
            const int r = ly + i;
            if (r < 32)
                tile[r][lx] = W[(size_t)(ty * 32 + r) * D_ + tx * 32 + lx];
        }
        __syncthreads();
#pragma unroll
        for (int i = 0; i < 36; i += 6) {
            const int r = ly + i;
            if (r < 32)
                wt[(size_t)(tx * 32 + r) * D_ + ty * 32 + lx] =
                    __float2half_rn(tile[lx][r]);
        }
        return;
    }

    // ---- gather row ----
    const int row = bid;
    const int b = row / S_;
    const int s = row - b * S_;
    const int t = tid;                  // 0..191, 4 elements each

    uint2* orow = (uint2*)(xs + (size_t)row * D_) + t;
    if (s == 0) {
        *orow = make_uint2(0u, 0u);
        if (t == 0) wsum[row] = 0.0f;
        return;
    }
    const int p = s - 1;
    const int id = img_ids[b];
    const float nx = noise[(size_t)(b * 2 + 0) * P_ + p];
    const float ny = noise[(size_t)(b * 2 + 1) * P_ + p];
    const size_t gb = (size_t)id * 2 * P_;
    const float ax = avgs[gb + p],  ay = avgs[gb + P_ + p];
    const float sx = stds[gb + p],  sy = stds[gb + P_ + p];

    const float kx = (nx - ax) / sx;
    const float ky = (ny - ay) / sy;
    const float x1 = ceilf(kx),  x2 = floorf(kx);
    const float y1 = ceilf(ky),  y2 = floorf(ky);
    const float wx1 = 1.0f - fabsf(x1 - kx);
    const float wx2 = 1.0f - fabsf(x2 - kx);
    const float wy1 = 1.0f - fabsf(y1 - ky);
    const float wy2 = 1.0f - fabsf(y2 - ky);
    const float w11 = wx1 * wy1, w21 = wx2 * wy1;
    const float w12 = wx1 * wy2, w22 = wx2 * wy2;

    const int i11 = wrap197((int)(14.0f * y1 + x1));
    const int i21 = wrap197((int)(14.0f * y1 + x2));
    const int i12 = wrap197((int)(14.0f * y2 + x1));
    const int i22 = wrap197((int)(14.0f * y2 + x2));

    const float4* xb = (const float4*)x + (size_t)b * S_ * (D_ / 4);
    const float4 a = xb[(size_t)i11 * (D_ / 4) + t];
    const float4 c = xb[(size_t)i21 * (D_ / 4) + t];
    const float4 d = xb[(size_t)i12 * (D_ / 4) + t];
    const float4 e = xb[(size_t)i22 * (D_ / 4) + t];

    float4 r;
    r.x = w11 * a.x + w21 * c.x + w12 * d.x + w22 * e.x;
    r.y = w11 * a.y + w21 * c.y + w12 * d.y + w22 * e.y;
    r.z = w11 * a.z + w21 * c.z + w12 * d.z + w22 * e.z;
    r.w = w11 * a.w + w21 * c.w + w12 * d.w + w22 * e.w;

    __half2 h0 = __floats2half2_rn(r.x, r.y);
    __half2 h1 = __floats2half2_rn(r.z, r.w);
    uint2 o;
    o.x = *(uint32_t*)&h0;
    o.y = *(uint32_t*)&h1;
    *orow = o;

    if (t == 0) wsum[row] = w11 + w21 + w12 + w22;
}

// ---------------------------------------------------------------------------
// FP16 tensor GEMM: out[M_,768] = xs @ Wt^T + wsum*bias (cls rows = 1.0)
// CTA 128x128, BK=64 (128B rows), 3-stage cp.async, single barrier/stage,
// 8 warps (2m x 4n), 64x32 warp tiles, ldmatrix.x4 fragment loads,
// XOR chunk swizzle (c ^ row&7). Persistent 592-CTA grid over 594 tiles.
// ---------------------------------------------------------------------------
#define BK     64
#define NSTG   12          // 768/64
#define STAGES 3
#define A_TILE 16384       // 128 rows * 128 bytes
#define STAGE_B (2 * A_TILE)               // 32768
#define SMEM_TOTAL (STAGES * STAGE_B)      // 98304
#define NTILES 594
#define GRID   592

__global__ __launch_bounds__(256) void gemm_f16(
    const __half* __restrict__ A, const __half* __restrict__ Bt,
    const float* __restrict__ bias, const float* __restrict__ wsum,
    float* __restrict__ C)
{
    extern __shared__ char smem[];
    const uint32_t sb = smem_u32(smem);

    const int tid  = threadIdx.x;
    const int wid  = tid >> 5;
    const int lane = tid & 31;
    const int g    = lane >> 2;       // 0..7
    const int t4   = lane & 3;        // 0..3
    const int wm   = wid & 1;         // 2 warp rows -> 64 m each
    const int wn   = wid >> 1;        // 4 warp cols -> 32 n each

    // cp.async maps: 1024 16B chunks per operand tile, 4 per thread
    // chunk ch: row = ch>>3, c = ch&7, swizzled dst = row*128 + ((c^(row&7))<<4)
    int arowi[4], dstoff[4];
#pragma unroll
    for (int i = 0; i < 4; i++) {
        const int ch  = tid + 256 * i;
        const int row = ch >> 3;
        const int c   = ch & 7;
        arowi[i]  = row;
        dstoff[i] = row * 128 + ((c ^ (row & 7)) << 4);
    }

    // ldmatrix lane address components
    const int aRowL = wm * 64 + ((lane >> 3) & 1) * 8 + (lane & 7);  // + fm*16
    const int aHi   = lane >> 4;                                     // chunk add
    const int bRowL = wn * 32 + (lane >> 4) * 8 + (lane & 7);        // + fnp*16
    const int bHi   = (lane >> 3) & 1;

    for (int tile = blockIdx.x; tile < NTILES; tile += GRID) {
        const int m0 = (tile / 6) * 128;
        const int n0 = (tile % 6) * 128;

        const __half* Ag[4];
        const __half* Bg[4];
#pragma unroll
        for (int i = 0; i < 4; i++) {
            int ga = m0 + arowi[i]; if (ga >= M_) ga = M_ - 1;
            Ag[i] = A  + (size_t)ga * D_ + (((tid + 256 * i) & 7) << 3);
            Bg[i] = Bt + (size_t)(n0 + arowi[i]) * D_ + (((tid + 256 * i) & 7) << 3);
        }

        float acc[4][4][4];
#pragma unroll
        for (int i = 0; i < 4; i++)
#pragma unroll
            for (int j = 0; j < 4; j++)
#pragma unroll
                for (int r = 0; r < 4; r++) acc[i][j][r] = 0.0f;

        // prologue: stages 0,1
#pragma unroll
        for (int s = 0; s < STAGES - 1; s++) {
            const int k0 = s * BK;
            const uint32_t so = (uint32_t)(s * STAGE_B);
#pragma unroll
            for (int i = 0; i < 4; i++) {
                cp_async16(sb + so + dstoff[i],          Ag[i] + k0);
                cp_async16(sb + so + A_TILE + dstoff[i], Bg[i] + k0);
            }
            CP_COMMIT();
        }

        int slot = 0;          // slot of stage s (s % 3, tracked incrementally)
        int pslot = 2;         // slot of stage s+2
        for (int s = 0; s < NSTG; s++) {
            CP_WAIT(1);            // stage s landed
            __syncthreads();       // all warps done reading slot pslot (= s-1 mod 3)

            const int sl = s + STAGES - 1;
            if (sl < NSTG) {
                const int k0 = sl * BK;
                const uint32_t so = (uint32_t)(pslot * STAGE_B);
#pragma unroll
                for (int i = 0; i < 4; i++) {
                    cp_async16(sb + so + dstoff[i],          Ag[i] + k0);
                    cp_async16(sb + so + A_TILE + dstoff[i], Bg[i] + k0);
                }
            }
            CP_COMMIT();

            const uint32_t AbO = sb + (uint32_t)(slot * STAGE_B);
            const uint32_t BbO = AbO + A_TILE;
#pragma unroll
            for (int ks = 0; ks < 4; ks++) {        // four k16 steps in BK=64
                uint32_t a[4][4], bb[2][4];
#pragma unroll
                for (int fm = 0; fm < 4; fm++) {
                    const int row = aRowL + fm * 16;
                    const int ck  = (2 * ks + aHi) ^ (row & 7);
                    ldsm_x4(a[fm], AbO + row * 128 + (ck << 4));
                }
#pragma unroll
                for (int fnp = 0; fnp < 2; fnp++) {
                    const int row = bRowL + fnp * 16;
                    const int ck  = (2 * ks + bHi) ^ (row & 7);
                    ldsm_x4(bb[fnp], BbO + row * 128 + (ck << 4));
                }
#pragma unroll
                for (int fm = 0; fm < 4; fm++) {
#pragma unroll
                    for (int fnp = 0; fnp < 2; fnp++) {
                        mma_f16(acc[fm][2 * fnp],     a[fm], &bb[fnp][0]);
                        mma_f16(acc[fm][2 * fnp + 1], a[fm], &bb[fnp][2]);
                    }
                }
            }
            slot  = (slot == 2)  ? 0 : slot + 1;
            pslot = (pslot == 2) ? 0 : pslot + 1;
        }

        // epilogue: out = acc + wsum[row]*bias[col]; class-token rows = 1.0
#pragma unroll
        for (int fm = 0; fm < 4; fm++) {
            const int row0 = m0 + wm * 64 + fm * 16 + g;
            const int row1 = row0 + 8;
            const bool ok0 = row0 < M_;
            const bool ok1 = row1 < M_;
            const bool cls0 = (row0 % S_) == 0;
            const bool cls1 = (row1 % S_) == 0;
            const float ws0 = ok0 ? wsum[row0] : 0.0f;
            const float ws1 = ok1 ? wsum[row1] : 0.0f;
#pragma unroll
            for (int fn = 0; fn < 4; fn++) {
                const int col = n0 + wn * 32 + fn * 8 + t4 * 2;
                const float b0 = bias[col];
                const float b1 = bias[col + 1];
                if (ok0) {
                    float2 o;
                    o.x = cls0 ? 1.0f : acc[fm][fn][0] + ws0 * b0;
                    o.y = cls0 ? 1.0f : acc[fm][fn][1] + ws0 * b1;
                    *(float2*)(C + (size_t)row0 * D_ + col) = o;
                }
                if (ok1) {
                    float2 o;
                    o.x = cls1 ? 1.0f : acc[fm][fn][2] + ws1 * b0;
                    o.y = cls1 ? 1.0f : acc[fm][fn][3] + ws1 * b1;
                    *(float2*)(C + (size_t)row1 * D_ + col) = o;
                }
            }
        }
        __syncthreads();   // smem reuse guard before next persistent tile
    }
}

// ---------------------------------------------------------------------------
// Inputs (metadata order): 0:x 1:img_ids 2:mask 3:Wq 4:bq 5:Wk 6:bk
//                          7:Wv 8:bv 9:avgs 10:std_devs 11:noise
// q/k/softmax are dead (softmax over singleton axis == 1): out = sampled v,
// and sampling commutes with the linear map -> gather x first, then one GEMM.
// ---------------------------------------------------------------------------
extern "C" void kernel_launch(void* const* d_in, const int* in_sizes, int n_in,
                              void* d_out, int out_size)
{
    const float* x       = (const float*)d_in[0];
    const int*   img_ids = (const int*)d_in[1];
    const float* Wv      = (const float*)d_in[7];
    const float* bv      = (const float*)d_in[8];
    const float* avgs    = (const float*)d_in[9];
    const float* stds    = (const float*)d_in[10];
    const float* noise   = (const float*)d_in[11];
    float* out = (float*)d_out;

    __half* xs = nullptr;
    __half* wt = nullptr;
    float*  ws = nullptr;
    cudaGetSymbolAddress((void**)&xs, g_xs);
    cudaGetSymbolAddress((void**)&wt, g_wt);
    cudaGetSymbolAddress((void**)&ws, g_ws);

    cudaFuncSetAttribute(gemm_f16, cudaFuncAttributeMaxDynamicSharedMemorySize,
                         SMEM_TOTAL);

    prep_kernel<<<M_ + 576, 192>>>(x, img_ids, avgs, stds, noise, Wv, xs, wt, ws);
    gemm_f16<<<GRID, 256, SMEM_TOTAL>>>(xs, wt, bv, ws, out);
}

// round 10
// speedup vs baseline: 1.9064x; 1.0065x over previous
#include <cuda_runtime.h>
#include <cuda_fp16.h>
#include <cstdint>

// Shapes (fixed by the problem)
#define B_ 64
#define S_ 197
#define D_ 768
#define P_ 196
#define M_ (B_ * S_)   // 12608 = 64 * 197

// Device scratch (no cudaMalloc allowed)
__device__ __half g_xs[(size_t)M_ * D_];    // weighted-gathered x, fp16
__device__ __half g_wt[(size_t)D_ * D_];    // Wv^T in fp16: g_wt[n][k]
__device__ float  g_ws[M_];                 // per-row weight sum

__device__ __forceinline__ uint32_t smem_u32(const void* p) {
    uint32_t a;
    asm("{ .reg .u64 t; cvta.to.shared.u64 t, %1; cvt.u32.u64 %0, t; }"
        : "=r"(a) : "l"(p));
    return a;
}
__device__ __forceinline__ void cp_async16(uint32_t dst, const void* src) {
    asm volatile("cp.async.cg.shared.global [%0], [%1], 16;"
                 :: "r"(dst), "l"(src));
}
#define CP_COMMIT() asm volatile("cp.async.commit_group;" ::: "memory")
#define CP_WAIT(n)  asm volatile("cp.async.wait_group %0;" :: "n"(n) : "memory")

__device__ __forceinline__ void ldsm_x4(uint32_t* r, uint32_t addr) {
    asm volatile("ldmatrix.sync.aligned.m8n8.x4.shared.b16 {%0,%1,%2,%3}, [%4];"
                 : "=r"(r[0]), "=r"(r[1]), "=r"(r[2]), "=r"(r[3]) : "r"(addr));
}
__device__ __forceinline__ void mma_f16(float* d, const uint32_t* a, const uint32_t* b)
{
    asm volatile(
        "mma.sync.aligned.m16n8k16.row.col.f32.f16.f16.f32 "
        "{%0,%1,%2,%3}, {%4,%5,%6,%7}, {%8,%9}, {%0,%1,%2,%3};"
        : "+f"(d[0]), "+f"(d[1]), "+f"(d[2]), "+f"(d[3])
        : "r"(a[0]), "r"(a[1]), "r"(a[2]), "r"(a[3]), "r"(b[0]), "r"(b[1]));
}

// ---------------------------------------------------------------------------
// Fused prep: blocks [0, M_) do the weighted gather of x -> xs (fp16) + wsum;
// blocks [M_, M_+576) transpose+convert Wv -> Wt[n][k] fp16.
// ---------------------------------------------------------------------------
__device__ __forceinline__ int wrap197(int i)
{
    int r = i % S_;
    return (r < 0) ? r + S_ : r;
}

__global__ __launch_bounds__(192) void prep_kernel(
    const float* __restrict__ x, const int* __restrict__ img_ids,
    const float* __restrict__ avgs, const float* __restrict__ stds,
    const float* __restrict__ noise, const float* __restrict__ W,
    __half* __restrict__ xs, __half* __restrict__ wt, float* __restrict__ wsum)
{
    __shared__ float tile[32][33];
    const int bid = blockIdx.x;
    const int tid = threadIdx.x;

    if (bid >= M_) {
        // ---- transpose tile of W ----
        const int t  = bid - M_;        // 0..575
        const int tx = t % 24;
        const int ty = t / 24;
        const int lx = tid & 31;
        const int ly = tid >> 5;        // 0..5
#pragma unroll
        for (int i = 0; i < 36; i += 6) {
            const int r = ly + i;
            if (r < 32)
                tile[r][lx] = W[(size_t)(ty * 32 + r) * D_ + tx * 32 + lx];
        }
        __syncthreads();
#pragma unroll
        for (int i = 0; i < 36; i += 6) {
            const int r = ly + i;
            if (r < 32)
                wt[(size_t)(tx * 32 + r) * D_ + ty * 32 + lx] =
                    __float2half_rn(tile[lx][r]);
        }
        return;
    }

    // ---- gather row ----
    const int row = bid;
    const int b = row / S_;
    const int s = row - b * S_;
    const int t = tid;                  // 0..191, 4 elements each

    uint2* orow = (uint2*)(xs + (size_t)row * D_) + t;
    if (s == 0) {
        *orow = make_uint2(0u, 0u);
        if (t == 0) wsum[row] = 0.0f;
        return;
    }
    const int p = s - 1;
    const int id = img_ids[b];
    const float nx = noise[(size_t)(b * 2 + 0) * P_ + p];
    const float ny = noise[(size_t)(b * 2 + 1) * P_ + p];
    const size_t gb = (size_t)id * 2 * P_;
    const float ax = avgs[gb + p],  ay = avgs[gb + P_ + p];
    const float sx = stds[gb + p],  sy = stds[gb + P_ + p];

    const float kx = (nx - ax) / sx;
    const float ky = (ny - ay) / sy;
    const float x1 = ceilf(kx),  x2 = floorf(kx);
    const float y1 = ceilf(ky),  y2 = floorf(ky);
    const float wx1 = 1.0f - fabsf(x1 - kx);
    const float wx2 = 1.0f - fabsf(x2 - kx);
    const float wy1 = 1.0f - fabsf(y1 - ky);
    const float wy2 = 1.0f - fabsf(y2 - ky);
    const float w11 = wx1 * wy1, w21 = wx2 * wy1;
    const float w12 = wx1 * wy2, w22 = wx2 * wy2;

    const int i11 = wrap197((int)(14.0f * y1 + x1));
    const int i21 = wrap197((int)(14.0f * y1 + x2));
    const int i12 = wrap197((int)(14.0f * y2 + x1));
    const int i22 = wrap197((int)(14.0f * y2 + x2));

    const float4* xb = (const float4*)x + (size_t)b * S_ * (D_ / 4);
    const float4 a = xb[(size_t)i11 * (D_ / 4) + t];
    const float4 c = xb[(size_t)i21 * (D_ / 4) + t];
    const float4 d = xb[(size_t)i12 * (D_ / 4) + t];
    const float4 e = xb[(size_t)i22 * (D_ / 4) + t];

    float4 r;
    r.x = w11 * a.x + w21 * c.x + w12 * d.x + w22 * e.x;
    r.y = w11 * a.y + w21 * c.y + w12 * d.y + w22 * e.y;
    r.z = w11 * a.z + w21 * c.z + w12 * d.z + w22 * e.z;
    r.w = w11 * a.w + w21 * c.w + w12 * d.w + w22 * e.w;

    __half2 h0 = __floats2half2_rn(r.x, r.y);
    __half2 h1 = __floats2half2_rn(r.z, r.w);
    uint2 o;
    o.x = *(uint32_t*)&h0;
    o.y = *(uint32_t*)&h1;
    *orow = o;

    if (t == 0) wsum[row] = w11 + w21 + w12 + w22;
}

// ---------------------------------------------------------------------------
// FP16 tensor GEMM: out[M_,768] = xs @ Wt^T + wsum*bias (cls rows = 1.0)
// CTA 128x128, BK=64 (128B rows), 3-stage cp.async, single barrier/stage.
// 4 warps (2m x 2n), 64x64 warp tiles -> 128 B of smem per mma (was 192).
// ldmatrix.x4 + XOR chunk swizzle (c ^ row&7). Persistent 592-CTA grid.
// ---------------------------------------------------------------------------
#define BK     64
#define NSTG   12          // 768/64
#define STAGES 3
#define A_TILE 16384       // 128 rows * 128 bytes
#define STAGE_B (2 * A_TILE)               // 32768
#define SMEM_TOTAL (STAGES * STAGE_B)      // 98304
#define NTILES 594
#define GRID   592

__global__ __launch_bounds__(128) void gemm_f16(
    const __half* __restrict__ A, const __half* __restrict__ Bt,
    const float* __restrict__ bias, const float* __restrict__ wsum,
    float* __restrict__ C)
{
    extern __shared__ char smem[];
    const uint32_t sb = smem_u32(smem);

    const int tid  = threadIdx.x;      // 0..127
    const int wid  = tid >> 5;         // 0..3
    const int lane = tid & 31;
    const int g    = lane >> 2;        // 0..7
    const int t4   = lane & 3;         // 0..3
    const int wm   = wid & 1;          // 2 warp rows -> 64 m each
    const int wn   = wid >> 1;         // 2 warp cols -> 64 n each

    // cp.async map: 1024 16B chunks per operand tile, 8 per thread.
    // chunk i: row = row0 + 16*i, col chunk c = tid&7 (invariant over i),
    // row&7 invariant over i -> swizzled dst = dst0 + i*2048.
    const int row0 = tid >> 3;               // 0..15
    const int cch  = tid & 7;                // 16B chunk column
    const uint32_t dst0 =
        (uint32_t)(row0 * 128 + ((cch ^ (row0 & 7)) << 4));

    // ldmatrix lane address components (same mapping as validated R9)
    const int aRowL = wm * 64 + ((lane >> 3) & 1) * 8 + (lane & 7);
    const int aHi   = lane >> 4;
    const int bRowL = wn * 64 + (lane >> 4) * 8 + (lane & 7);
    const int bHi   = (lane >> 3) & 1;

    for (int tile = blockIdx.x; tile < NTILES; tile += GRID) {
        const int m0 = (tile / 6) * 128;
        const int n0 = (tile % 6) * 128;

        // global element offsets (fit in int: max ~9.7M)
        int aOff[8];
#pragma unroll
        for (int i = 0; i < 8; i++) {
            int ga = m0 + row0 + 16 * i;
            if (ga >= M_) ga = M_ - 1;
            aOff[i] = ga * D_ + cch * 8;
        }
        const int bOff0 = (n0 + row0) * D_ + cch * 8;   // + i*16*D_

        float acc[4][8][4];
#pragma unroll
        for (int i = 0; i < 4; i++)
#pragma unroll
            for (int j = 0; j < 8; j++)
#pragma unroll
                for (int r = 0; r < 4; r++) acc[i][j][r] = 0.0f;

        // prologue: stages 0,1
#pragma unroll
        for (int s = 0; s < STAGES - 1; s++) {
            const int k0 = s * BK;
            const uint32_t so = (uint32_t)(s * STAGE_B) + dst0;
#pragma unroll
            for (int i = 0; i < 8; i++) {
                cp_async16(sb + so + i * 2048,          A  + aOff[i] + k0);
                cp_async16(sb + so + A_TILE + i * 2048, Bt + bOff0 + i * (16 * D_) + k0);
            }
            CP_COMMIT();
        }

        int slot = 0, pslot = 2;
        for (int s = 0; s < NSTG; s++) {
            CP_WAIT(1);            // stage s landed
            __syncthreads();       // all warps done reading slot pslot

            const int sl = s + STAGES - 1;
            if (sl < NSTG) {
                const int k0 = sl * BK;
                const uint32_t so = (uint32_t)(pslot * STAGE_B) + dst0;
#pragma unroll
                for (int i = 0; i < 8; i++) {
                    cp_async16(sb + so + i * 2048,          A  + aOff[i] + k0);
                    cp_async16(sb + so + A_TILE + i * 2048, Bt + bOff0 + i * (16 * D_) + k0);
                }
            }
            CP_COMMIT();

            const uint32_t AbO = sb + (uint32_t)(slot * STAGE_B);
            const uint32_t BbO = AbO + A_TILE;
#pragma unroll
            for (int ks = 0; ks < 4; ks++) {        // four k16 steps in BK=64
                uint32_t a[4][4], bb[4][4];
#pragma unroll
                for (int fm = 0; fm < 4; fm++) {
                    const int row = aRowL + fm * 16;
                    const int ck  = (2 * ks + aHi) ^ (row & 7);
                    ldsm_x4(a[fm], AbO + row * 128 + (ck << 4));
                }
#pragma unroll
                for (int fnp = 0; fnp < 4; fnp++) {
                    const int row = bRowL + fnp * 16;
                    const int ck  = (2 * ks + bHi) ^ (row & 7);
                    ldsm_x4(bb[fnp], BbO + row * 128 + (ck << 4));
                }
#pragma unroll
                for (int fm = 0; fm < 4; fm++) {
#pragma unroll
                    for (int fnp = 0; fnp < 4; fnp++) {
                        mma_f16(acc[fm][2 * fnp],     a[fm], &bb[fnp][0]);
                        mma_f16(acc[fm][2 * fnp + 1], a[fm], &bb[fnp][2]);
                    }
                }
            }
            slot  = (slot == 2)  ? 0 : slot + 1;
            pslot = (pslot == 2) ? 0 : pslot + 1;
        }

        // epilogue: out = acc + wsum[row]*bias[col]; class-token rows = 1.0
#pragma unroll
        for (int fm = 0; fm < 4; fm++) {
            const int row0e = m0 + wm * 64 + fm * 16 + g;
            const int row1e = row0e + 8;
            const bool ok0 = row0e < M_;
            const bool ok1 = row1e < M_;
            const bool cls0 = (row0e % S_) == 0;
            const bool cls1 = (row1e % S_) == 0;
            const float ws0 = ok0 ? wsum[row0e] : 0.0f;
            const float ws1 = ok1 ? wsum[row1e] : 0.0f;
#pragma unroll
            for (int fn = 0; fn < 8; fn++) {
                const int col = n0 + wn * 64 + fn * 8 + t4 * 2;
                const float b0 = bias[col];
                const float b1 = bias[col + 1];
                if (ok0) {
                    float2 o;
                    o.x = cls0 ? 1.0f : acc[fm][fn][0] + ws0 * b0;
                    o.y = cls0 ? 1.0f : acc[fm][fn][1] + ws0 * b1;
                    *(float2*)(C + (size_t)row0e * D_ + col) = o;
                }
                if (ok1) {
                    float2 o;
                    o.x = cls1 ? 1.0f : acc[fm][fn][2] + ws1 * b0;
                    o.y = cls1 ? 1.0f : acc[fm][fn][3] + ws1 * b1;
                    *(float2*)(C + (size_t)row1e * D_ + col) = o;
                }
            }
        }
        __syncthreads();   // smem reuse guard before next persistent tile
    }
}

// ---------------------------------------------------------------------------
// Inputs (metadata order): 0:x 1:img_ids 2:mask 3:Wq 4:bq 5:Wk 6:bk
//                          7:Wv 8:bv 9:avgs 10:std_devs 11:noise
// q/k/softmax are dead (softmax over singleton axis == 1): out = sampled v,
// and sampling commutes with the linear map -> gather x first, then one GEMM.
// ---------------------------------------------------------------------------
extern "C" void kernel_launch(void* const* d_in, const int* in_sizes, int n_in,
                              void* d_out, int out_size)
{
    const float* x       = (const float*)d_in[0];
    const int*   img_ids = (const int*)d_in[1];
    const float* Wv      = (const float*)d_in[7];
    const float* bv      = (const float*)d_in[8];
    const float* avgs    = (const float*)d_in[9];
    const float* stds    = (const float*)d_in[10];
    const float* noise   = (const float*)d_in[11];
    float* out = (float*)d_out;

    __half* xs = nullptr;
    __half* wt = nullptr;
    float*  ws = nullptr;
    cudaGetSymbolAddress((void**)&xs, g_xs);
    cudaGetSymbolAddress((void**)&wt, g_wt);
    cudaGetSymbolAddress((void**)&ws, g_ws);

    cudaFuncSetAttribute(gemm_f16, cudaFuncAttributeMaxDynamicSharedMemorySize,
                         SMEM_TOTAL);

    prep_kernel<<<M_ + 576, 192>>>(x, img_ids, avgs, stds, noise, Wv, xs, wt, ws);
    gemm_f16<<<GRID, 128, SMEM_TOTAL>>>(xs, wt, bv, ws, out);
}

// round 11
// speedup vs baseline: 2.0486x; 1.0746x over previous
#include <cuda_runtime.h>
#include <cuda_fp16.h>
#include <cstdint>

// Shapes (fixed by the problem)
#define B_ 64
#define S_ 197
#define D_ 768
#define P_ 196
#define M_ (B_ * S_)   // 12608 = 64 * 197

// Device scratch (no cudaMalloc allowed)
__device__ __half g_xs[(size_t)M_ * D_];    // weighted-gathered x, fp16
__device__ __half g_wt[(size_t)D_ * D_];    // Wv^T in fp16: g_wt[n][k]
__device__ float  g_ws[M_];                 // per-row weight sum

__device__ __forceinline__ uint32_t smem_u32(const void* p) {
    uint32_t a;
    asm("{ .reg .u64 t; cvta.to.shared.u64 t, %1; cvt.u32.u64 %0, t; }"
        : "=r"(a) : "l"(p));
    return a;
}
__device__ __forceinline__ void cp_async16(uint32_t dst, const void* src) {
    asm volatile("cp.async.cg.shared.global [%0], [%1], 16;"
                 :: "r"(dst), "l"(src));
}
#define CP_COMMIT() asm volatile("cp.async.commit_group;" ::: "memory")
#define CP_WAIT(n)  asm volatile("cp.async.wait_group %0;" :: "n"(n) : "memory")

__device__ __forceinline__ void ldsm_x4(uint32_t* r, uint32_t addr) {
    asm volatile("ldmatrix.sync.aligned.m8n8.x4.shared.b16 {%0,%1,%2,%3}, [%4];"
                 : "=r"(r[0]), "=r"(r[1]), "=r"(r[2]), "=r"(r[3]) : "r"(addr));
}
__device__ __forceinline__ void mma_f16(float* d, const uint32_t* a, const uint32_t* b)
{
    asm volatile(
        "mma.sync.aligned.m16n8k16.row.col.f32.f16.f16.f32 "
        "{%0,%1,%2,%3}, {%4,%5,%6,%7}, {%8,%9}, {%0,%1,%2,%3};"
        : "+f"(d[0]), "+f"(d[1]), "+f"(d[2]), "+f"(d[3])
        : "r"(a[0]), "r"(a[1]), "r"(a[2]), "r"(a[3]), "r"(b[0]), "r"(b[1]));
}

// ---------------------------------------------------------------------------
// Fused prep: blocks [0, M_) do the weighted gather of x -> xs (fp16) + wsum;
// blocks [M_, M_+576) transpose+convert Wv -> Wt[n][k] fp16.
// ---------------------------------------------------------------------------
__device__ __forceinline__ int wrap197(int i)
{
    int r = i % S_;
    return (r < 0) ? r + S_ : r;
}

__global__ __launch_bounds__(192) void prep_kernel(
    const float* __restrict__ x, const int* __restrict__ img_ids,
    const float* __restrict__ avgs, const float* __restrict__ stds,
    const float* __restrict__ noise, const float* __restrict__ W,
    __half* __restrict__ xs, __half* __restrict__ wt, float* __restrict__ wsum)
{
    __shared__ float tile[32][33];
    const int bid = blockIdx.x;
    const int tid = threadIdx.x;

    if (bid >= M_) {
        // ---- transpose tile of W ----
        const int t  = bid - M_;        // 0..575
        const int tx = t % 24;
        const int ty = t / 24;
        const int lx = tid & 31;
        const int ly = tid >> 5;        // 0..5
#pragma unroll
        for (int i = 0; i < 36; i += 6) {
            const int r = ly + i;
            if (r < 32)
                tile[r][lx] = W[(size_t)(ty * 32 + r) * D_ + tx * 32 + lx];
        }
        __syncthreads();
#pragma unroll
        for (int i = 0; i < 36; i += 6) {
            const int r = ly + i;
            if (r < 32)
                wt[(size_t)(tx * 32 + r) * D_ + ty * 32 + lx] =
                    __float2half_rn(tile[lx][r]);
        }
        return;
    }

    // ---- gather row ----
    const int row = bid;
    const int b = row / S_;
    const int s = row - b * S_;
    const int t = tid;                  // 0..191, 4 elements each

    uint2* orow = (uint2*)(xs + (size_t)row * D_) + t;
    if (s == 0) {
        *orow = make_uint2(0u, 0u);
        if (t == 0) wsum[row] = 0.0f;
        return;
    }
    const int p = s - 1;
    const int id = img_ids[b];
    const float nx = noise[(size_t)(b * 2 + 0) * P_ + p];
    const float ny = noise[(size_t)(b * 2 + 1) * P_ + p];
    const size_t gb = (size_t)id * 2 * P_;
    const float ax = avgs[gb + p],  ay = avgs[gb + P_ + p];
    const float sx = stds[gb + p],  sy = stds[gb + P_ + p];

    const float kx = (nx - ax) / sx;
    const float ky = (ny - ay) / sy;
    const float x1 = ceilf(kx),  x2 = floorf(kx);
    const float y1 = ceilf(ky),  y2 = floorf(ky);
    const float wx1 = 1.0f - fabsf(x1 - kx);
    const float wx2 = 1.0f - fabsf(x2 - kx);
    const float wy1 = 1.0f - fabsf(y1 - ky);
    const float wy2 = 1.0f - fabsf(y2 - ky);
    const float w11 = wx1 * wy1, w21 = wx2 * wy1;
    const float w12 = wx1 * wy2, w22 = wx2 * wy2;

    const int i11 = wrap197((int)(14.0f * y1 + x1));
    const int i21 = wrap197((int)(14.0f * y1 + x2));
    const int i12 = wrap197((int)(14.0f * y2 + x1));
    const int i22 = wrap197((int)(14.0f * y2 + x2));

    const float4* xb = (const float4*)x + (size_t)b * S_ * (D_ / 4);
    const float4 a = xb[(size_t)i11 * (D_ / 4) + t];
    const float4 c = xb[(size_t)i21 * (D_ / 4) + t];
    const float4 d = xb[(size_t)i12 * (D_ / 4) + t];
    const float4 e = xb[(size_t)i22 * (D_ / 4) + t];

    float4 r;
    r.x = w11 * a.x + w21 * c.x + w12 * d.x + w22 * e.x;
    r.y = w11 * a.y + w21 * c.y + w12 * d.y + w22 * e.y;
    r.z = w11 * a.z + w21 * c.z + w12 * d.z + w22 * e.z;
    r.w = w11 * a.w + w21 * c.w + w12 * d.w + w22 * e.w;

    __half2 h0 = __floats2half2_rn(r.x, r.y);
    __half2 h1 = __floats2half2_rn(r.z, r.w);
    uint2 o;
    o.x = *(uint32_t*)&h0;
    o.y = *(uint32_t*)&h1;
    *orow = o;

    if (t == 0) wsum[row] = w11 + w21 + w12 + w22;
}

// ---------------------------------------------------------------------------
// FP16 tensor GEMM: out[M_,768] = xs @ Wt^T + wsum*bias (cls rows = 1.0)
// CTA 128x128, BK=64 (128B rows), 3-stage cp.async, single barrier/stage.
// 4 warps (2m x 2n), 64x64 warp tiles, ldmatrix.x4, XOR chunk swizzle.
// Software-pipelined fragments: ldsm(ks+1) issued before mma(ks) so the
// tensor pipe never waits on LDS latency inside a stage.
// Persistent 592-CTA grid over 594 tiles (2 clean waves).
// ---------------------------------------------------------------------------
#define BK     64
#define NSTG   12          // 768/64
#define STAGES 3
#define A_TILE 16384       // 128 rows * 128 bytes
#define STAGE_B (2 * A_TILE)               // 32768
#define SMEM_TOTAL (STAGES * STAGE_B)      // 98304
#define NTILES 594
#define GRID   592

__global__ __launch_bounds__(128) void gemm_f16(
    const __half* __restrict__ A, const __half* __restrict__ Bt,
    const float* __restrict__ bias, const float* __restrict__ wsum,
    float* __restrict__ C)
{
    extern __shared__ char smem[];
    const uint32_t sb = smem_u32(smem);

    const int tid  = threadIdx.x;      // 0..127
    const int wid  = tid >> 5;         // 0..3
    const int lane = tid & 31;
    const int g    = lane >> 2;        // 0..7
    const int t4   = lane & 3;         // 0..3
    const int wm   = wid & 1;          // 2 warp rows -> 64 m each
    const int wn   = wid >> 1;         // 2 warp cols -> 64 n each

    // cp.async map: 1024 16B chunks per operand tile, 8 per thread.
    const int row0 = tid >> 3;               // 0..15
    const int cch  = tid & 7;                // 16B chunk column
    const uint32_t dst0 =
        (uint32_t)(row0 * 128 + ((cch ^ (row0 & 7)) << 4));

    // ldmatrix lane address components
    const int aRowL = wm * 64 + ((lane >> 3) & 1) * 8 + (lane & 7);
    const int aHi   = lane >> 4;
    const int bRowL = wn * 64 + (lane >> 4) * 8 + (lane & 7);
    const int bHi   = (lane >> 3) & 1;

    // precomputed swizzled row bases (row*128) and selectors
    uint32_t aBase[4], bBase[4];
    int aSel[4], bSel[4];
#pragma unroll
    for (int f = 0; f < 4; f++) {
        const int ar = aRowL + f * 16;
        const int br = bRowL + f * 16;
        aBase[f] = (uint32_t)(ar * 128);
        bBase[f] = (uint32_t)(br * 128);
        aSel[f]  = ar & 7;
        bSel[f]  = br & 7;
    }

    for (int tile = blockIdx.x; tile < NTILES; tile += GRID) {
        const int m0 = (tile / 6) * 128;
        const int n0 = (tile % 6) * 128;

        int aOff[8];
#pragma unroll
        for (int i = 0; i < 8; i++) {
            int ga = m0 + row0 + 16 * i;
            if (ga >= M_) ga = M_ - 1;
            aOff[i] = ga * D_ + cch * 8;
        }
        const int bOff0 = (n0 + row0) * D_ + cch * 8;   // + i*16*D_

        float acc[4][8][4];
#pragma unroll
        for (int i = 0; i < 4; i++)
#pragma unroll
            for (int j = 0; j < 8; j++)
#pragma unroll
                for (int r = 0; r < 4; r++) acc[i][j][r] = 0.0f;

        // prologue: stages 0,1
#pragma unroll
        for (int s = 0; s < STAGES - 1; s++) {
            const int k0 = s * BK;
            const uint32_t so = (uint32_t)(s * STAGE_B) + dst0;
#pragma unroll
            for (int i = 0; i < 8; i++) {
                cp_async16(sb + so + i * 2048,          A  + aOff[i] + k0);
                cp_async16(sb + so + A_TILE + i * 2048, Bt + bOff0 + i * (16 * D_) + k0);
            }
            CP_COMMIT();
        }

        uint32_t a[2][4][4], bb[2][4][4];   // double-buffered fragments
        int slot = 0, pslot = 2;
        for (int s = 0; s < NSTG; s++) {
            CP_WAIT(1);            // stage s landed
            __syncthreads();       // all warps done reading slot pslot

            const uint32_t AbO = sb + (uint32_t)(slot * STAGE_B);
            const uint32_t BbO = AbO + A_TILE;

            // load ks=0 fragments first (start the tensor pipe ASAP)
#pragma unroll
            for (int f = 0; f < 4; f++) {
                ldsm_x4(a[0][f],  AbO + aBase[f] + ((aHi ^ aSel[f]) << 4));
                ldsm_x4(bb[0][f], BbO + bBase[f] + ((bHi ^ bSel[f]) << 4));
            }

            // then issue next-stage cp.async (overlaps with mma below)
            const int sl = s + STAGES - 1;
            if (sl < NSTG) {
                const int k0 = sl * BK;
                const uint32_t so = (uint32_t)(pslot * STAGE_B) + dst0;
#pragma unroll
                for (int i = 0; i < 8; i++) {
                    cp_async16(sb + so + i * 2048,          A  + aOff[i] + k0);
                    cp_async16(sb + so + A_TILE + i * 2048, Bt + bOff0 + i * (16 * D_) + k0);
                }
            }
            CP_COMMIT();

#pragma unroll
            for (int ks = 0; ks < 4; ks++) {        // four k16 steps in BK=64
                const int cur = ks & 1;
                const int nxt = cur ^ 1;
                if (ks < 3) {                       // prefetch ks+1 fragments
                    const int kc = 2 * (ks + 1);
#pragma unroll
                    for (int f = 0; f < 4; f++) {
                        ldsm_x4(a[nxt][f],  AbO + aBase[f] + (((kc + aHi) ^ aSel[f]) << 4));
                        ldsm_x4(bb[nxt][f], BbO + bBase[f] + (((kc + bHi) ^ bSel[f]) << 4));
                    }
                }
#pragma unroll
                for (int fm = 0; fm < 4; fm++) {
#pragma unroll
                    for (int fnp = 0; fnp < 4; fnp++) {
                        mma_f16(acc[fm][2 * fnp],     a[cur][fm], &bb[cur][fnp][0]);
                        mma_f16(acc[fm][2 * fnp + 1], a[cur][fm], &bb[cur][fnp][2]);
                    }
                }
            }
            slot  = (slot == 2)  ? 0 : slot + 1;
            pslot = (pslot == 2) ? 0 : pslot + 1;
        }

        // epilogue: out = acc + wsum[row]*bias[col]; class-token rows = 1.0
#pragma unroll
        for (int fm = 0; fm < 4; fm++) {
            const int row0e = m0 + wm * 64 + fm * 16 + g;
            const int row1e = row0e + 8;
            const bool ok0 = row0e < M_;
            const bool ok1 = row1e < M_;
            const bool cls0 = (row0e % S_) == 0;
            const bool cls1 = (row1e % S_) == 0;
            const float ws0 = ok0 ? wsum[row0e] : 0.0f;
            const float ws1 = ok1 ? wsum[row1e] : 0.0f;
#pragma unroll
            for (int fn = 0; fn < 8; fn++) {
                const int col = n0 + wn * 64 + fn * 8 + t4 * 2;
                const float b0 = bias[col];
                const float b1 = bias[col + 1];
                if (ok0) {
                    float2 o;
                    o.x = cls0 ? 1.0f : acc[fm][fn][0] + ws0 * b0;
                    o.y = cls0 ? 1.0f : acc[fm][fn][1] + ws0 * b1;
                    *(float2*)(C + (size_t)row0e * D_ + col) = o;
                }
                if (ok1) {
                    float2 o;
                    o.x = cls1 ? 1.0f : acc[fm][fn][2] + ws1 * b0;
                    o.y = cls1 ? 1.0f : acc[fm][fn][3] + ws1 * b1;
                    *(float2*)(C + (size_t)row1e * D_ + col) = o;
                }
            }
        }
        __syncthreads();   // smem reuse guard before next persistent tile
    }
}

// ---------------------------------------------------------------------------
// Inputs (metadata order): 0:x 1:img_ids 2:mask 3:Wq 4:bq 5:Wk 6:bk
//                          7:Wv 8:bv 9:avgs 10:std_devs 11:noise
// q/k/softmax are dead (softmax over singleton axis == 1): out = sampled v,
// and sampling commutes with the linear map -> gather x first, then one GEMM.
// ---------------------------------------------------------------------------
extern "C" void kernel_launch(void* const* d_in, const int* in_sizes, int n_in,
                              void* d_out, int out_size)
{
    const float* x       = (const float*)d_in[0];
    const int*   img_ids = (const int*)d_in[1];
    const float* Wv      = (const float*)d_in[7];
    const float* bv      = (const float*)d_in[8];
    const float* avgs    = (const float*)d_in[9];
    const float* stds    = (const float*)d_in[10];
    const float* noise   = (const float*)d_in[11];
    float* out = (float*)d_out;

    __half* xs = nullptr;
    __half* wt = nullptr;
    float*  ws = nullptr;
    cudaGetSymbolAddress((void**)&xs, g_xs);
    cudaGetSymbolAddress((void**)&wt, g_wt);
    cudaGetSymbolAddress((void**)&ws, g_ws);

    cudaFuncSetAttribute(gemm_f16, cudaFuncAttributeMaxDynamicSharedMemorySize,
                         SMEM_TOTAL);

    prep_kernel<<<M_ + 576, 192>>>(x, img_ids, avgs, stds, noise, Wv, xs, wt, ws);
    gemm_f16<<<GRID, 128, SMEM_TOTAL>>>(xs, wt, bv, ws, out);
}